// round 9
// baseline (speedup 1.0000x reference)
#include <cuda_runtime.h>
#include <cfloat>

#define TOT 8192
#define BN 16
#define C 64
#define K 20
#define CN 512
#define NW (BN*CN)
#define STEPS 8
#define BN_EPS 1e-5f

// ---- device scratch (static; no allocations) ----
__device__ float  g_xT[(size_t)BN*TOT*C];        // x transposed (b,node,ch) 32MB
__device__ float2 g_ssq[(size_t)BN*TOT];         // per-node (dot(x,w_lo), |x|^2)
__device__ float  g_curves[(size_t)STEPS*NW*C];  // [step][w][ch] 16MB
__device__ float  g_curf[(size_t)NW*C];
__device__ float  g_pref[(size_t)NW*C];
__device__ int    g_curidx[NW];
__device__ float  g_S[BN*2*CN];                  // softmax exchange

__device__ __forceinline__ float dot4(const float4& a, const float4& b) {
    return a.x*b.x + a.y*b.y + a.z*b.z + a.w*b.w;
}

// ---------------- fused prep: transpose + per-node (s, |x|^2) ----------------
// 256 thr = 16 nodes x 16 lanes; lane j owns channels [4j..4j+3].
// 16-lane butterfly tree MUST match the walk kernel's cf2/cfp tree (exactness).
__global__ __launch_bounds__(256)
void prep_kernel(const float* __restrict__ x, const float* __restrict__ agent_w) {
    __shared__ float tile[64][17];
    int b = blockIdx.y;
    int node0 = blockIdx.x * 16;
    int t = threadIdx.x;
    int ty = t >> 2;     // channel 0..63
    int tx = t & 3;      // float4 along nodes (16 nodes = 4 float4)

    const float4* src = (const float4*)(x + (size_t)b * C * TOT
                                          + (size_t)ty * TOT + node0);
    float4 v = __ldg(&src[tx]);
    tile[ty][tx*4+0] = v.x; tile[ty][tx*4+1] = v.y;
    tile[ty][tx*4+2] = v.z; tile[ty][tx*4+3] = v.w;
    __syncthreads();

    int node = t >> 4;   // 0..15
    int j = t & 15;      // channel float4 group
    float4 a = make_float4(tile[4*j+0][node], tile[4*j+1][node],
                           tile[4*j+2][node], tile[4*j+3][node]);
    ((float4*)(g_xT + ((size_t)b * TOT + node0 + node) * C))[j] = a;

    const float4* wv = (const float4*)agent_w;
    float s = dot4(a, __ldg(&wv[j]));
    float q = dot4(a, a);
    #pragma unroll
    for (int off = 1; off <= 8; off <<= 1) {
        s += __shfl_xor_sync(0xffffffffu, s, off);
        q += __shfl_xor_sync(0xffffffffu, q, off);
    }
    if (j == 0) g_ssq[(size_t)b * TOT + node0 + node] = make_float2(s, q);
}

// ---------------- one walk step; 16 lanes/walker, 8 walkers/block ----------------
// lane sub (0..15) owns channels [4*sub..4*sub+3].
template<bool FIRST>
__global__ __launch_bounds__(128, 5)
void walk_step_kernel(
    const int* __restrict__ adj, const int* __restrict__ cur0,
    const float* __restrict__ agent_w,
    const float* __restrict__ agent_gamma, const float* __restrict__ agent_beta,
    const float* __restrict__ agent_mean,  const float* __restrict__ agent_var,
    const float* __restrict__ mom_w,
    const float* __restrict__ mom_gamma, const float* __restrict__ mom_beta,
    const float* __restrict__ mom_mean,  const float* __restrict__ mom_var,
    int step)
{
    int sub = threadIdx.x & 15;
    int w = blockIdx.x * 8 + (threadIdx.x >> 4);
    int b = w >> 9;
    int n = w & 511;

    const float4* wv = (const float4*)agent_w;
    float4 wh = __ldg(&wv[16 + sub]);              // agent_w[64:128], group sub

    float inv_a  = __ldg(agent_gamma) / sqrtf(__ldg(agent_var) + BN_EPS);
    float mean_a = __ldg(agent_mean);
    float beta_a = __ldg(agent_beta);

    const float* xTb = g_xT + (size_t)b * TOT * C;
    const float2* ssqb = g_ssq + (size_t)b * TOT;

    float4 cf4, pf4, cv4;
    int cidx;
    float tpp, n1 = 0.f, cvcf = 0.f, cf2 = 0.f;

    if (FIRST) {
        cidx = __ldg(&cur0[w]);
        pf4 = __ldg(&((const float4*)(xTb + (size_t)cidx * C))[sub]);
        tpp = dot4(pf4, wh);
        #pragma unroll
        for (int off = 1; off <= 8; off <<= 1)
            tpp += __shfl_xor_sync(0xffffffffu, tpp, off);
        cf4 = make_float4(0.f,0.f,0.f,0.f); cv4 = cf4;
    } else {
        cidx = g_curidx[w];
        cf4 = ((const float4*)(g_curf + (size_t)w * C))[sub];
        pf4 = ((const float4*)(g_pref + (size_t)w * C))[sub];
        float2 aa = ((const float2*)g_S)[b * 512 + n];   // entries 2n, 2n+1
        float a0 = aa.x, a1 = aa.y;
        pf4.x = cf4.x*a0 + pf4.x*a1;  pf4.y = cf4.y*a0 + pf4.y*a1;
        pf4.z = cf4.z*a0 + pf4.z*a1;  pf4.w = cf4.w*a0 + pf4.w*a1;
        cv4.x = cf4.x - pf4.x; cv4.y = cf4.y - pf4.y;
        cv4.z = cf4.z - pf4.z; cv4.w = cf4.w - pf4.w;

        float tppp  = dot4(pf4, wh);
        float n1pp  = dot4(cv4, cv4);
        float cvcfp = dot4(cv4, cf4);
        float cf2p  = dot4(cf4, cf4);
        #pragma unroll
        for (int off = 1; off <= 8; off <<= 1) {
            tppp  += __shfl_xor_sync(0xffffffffu, tppp, off);
            n1pp  += __shfl_xor_sync(0xffffffffu, n1pp, off);
            cvcfp += __shfl_xor_sync(0xffffffffu, cvcfp, off);
            cf2p  += __shfl_xor_sync(0xffffffffu, cf2p, off);
        }
        tpp = tppp; n1 = sqrtf(n1pp); cvcf = cvcfp; cf2 = cf2p;
    }

    const int* adjp = adj + ((size_t)b * TOT + cidx) * K;
    const int4* adj4 = (const int4*)adjp;

    // ---- distributed ssq loads: lane k owns q for k (k<16), lanes 0-3 own 16+ ----
    int oa0 = __ldg(&adjp[sub]);
    int oa1 = (sub < 4) ? __ldg(&adjp[16 + sub]) : oa0;
    float2 q0 = __ldg(&ssqb[oa0]);
    float2 q1 = __ldg(&ssqb[oa1]);

    float best = -FLT_MAX; int ksel = 0;

    if (FIRST) {
        #pragma unroll
        for (int k = 0; k < K; k++) {
            float sx = (k < 16) ? __shfl_sync(0xffffffffu, q0.x, k, 16)
                                : __shfl_sync(0xffffffffu, q1.x, k - 16, 16);
            float lg = (sx + tpp - mean_a) * inv_a + beta_a;
            if (lg > best) { best = lg; ksel = k; }
        }
    } else {
        // ---- batched gathers: 20 coalesced 256B rows, full MLP ----
        float cvp[K], cfp[K];
        #pragma unroll
        for (int q = 0; q < 5; q++) {
            int4 t4 = __ldg(&adj4[q]);
            float4 p0 = __ldg(&((const float4*)(xTb + (size_t)t4.x * C))[sub]);
            float4 p1 = __ldg(&((const float4*)(xTb + (size_t)t4.y * C))[sub]);
            float4 p2 = __ldg(&((const float4*)(xTb + (size_t)t4.z * C))[sub]);
            float4 p3 = __ldg(&((const float4*)(xTb + (size_t)t4.w * C))[sub]);
            cvp[4*q+0] = dot4(cv4, p0); cfp[4*q+0] = dot4(cf4, p0);
            cvp[4*q+1] = dot4(cv4, p1); cfp[4*q+1] = dot4(cf4, p1);
            cvp[4*q+2] = dot4(cv4, p2); cfp[4*q+2] = dot4(cf4, p2);
            cvp[4*q+3] = dot4(cv4, p3); cfp[4*q+3] = dot4(cf4, p3);
        }
        // ---- 16-lane butterfly: all lanes end with full sums (validated shape) ----
        #pragma unroll
        for (int off = 1; off <= 8; off <<= 1) {
            #pragma unroll
            for (int k = 0; k < K; k++) {
                cvp[k] += __shfl_xor_sync(0xffffffffu, cvp[k], off);
                cfp[k] += __shfl_xor_sync(0xffffffffu, cfp[k], off);
            }
        }
        // ---- redundant epilogue, constant indexing, q via broadcast ----
        #pragma unroll
        for (int k = 0; k < K; k++) {
            float sx, sy;
            if (k < 16) {
                sx = __shfl_sync(0xffffffffu, q0.x, k, 16);
                sy = __shfl_sync(0xffffffffu, q0.y, k, 16);
            } else {
                sx = __shfl_sync(0xffffffffu, q1.x, k - 16, 16);
                sy = __shfl_sync(0xffffffffu, q1.y, k - 16, 16);
            }
            float lg = (sx + tpp - mean_a) * inv_a + beta_a;
            float cc = cvp[k] - cvcf;
            float nn = sy - 2.f * cfp[k] + cf2;
            float cosv = cc / fmaxf(n1 * sqrtf(nn), 1e-8f);
            lg *= fminf(fmaxf(1.f + cosv, 0.f), 1.f);
            if (lg > best) { best = lg; ksel = k; }
        }
    }

    int nidx = __ldg(&adjp[ksel]);
    cf4 = __ldg(&((const float4*)(xTb + (size_t)nidx * C))[sub]);

    // ---- coalesced curve store + persist state (256B rows) ----
    ((float4*)(g_curves + ((size_t)step * NW + w) * C))[sub] = cf4;
    ((float4*)(g_curf + (size_t)w * C))[sub] = cf4;
    ((float4*)(g_pref + (size_t)w * C))[sub] = pf4;
    if (sub == 0) g_curidx[w] = nidx;

    if (step < STEPS - 1) {
        const float4* mv = (const float4*)mom_w;   // 2 rows x 32 float4
        float l0 = dot4(cf4, __ldg(&mv[sub]))      + dot4(pf4, __ldg(&mv[16 + sub]));
        float l1 = dot4(cf4, __ldg(&mv[32 + sub])) + dot4(pf4, __ldg(&mv[48 + sub]));
        #pragma unroll
        for (int off = 1; off <= 8; off <<= 1) {
            l0 += __shfl_xor_sync(0xffffffffu, l0, off);
            l1 += __shfl_xor_sync(0xffffffffu, l1, off);
        }
        if (sub == 0) {
            float inv0 = __ldg(&mom_gamma[0]) / sqrtf(__ldg(&mom_var[0]) + BN_EPS);
            float inv1 = __ldg(&mom_gamma[1]) / sqrtf(__ldg(&mom_var[1]) + BN_EPS);
            float m0 = (l0 - __ldg(&mom_mean[0])) * inv0 + __ldg(&mom_beta[0]);
            float m1 = (l1 - __ldg(&mom_mean[1])) * inv1 + __ldg(&mom_beta[1]);
            float mx = fmaxf(m0, m1);
            float e0 = expf(m0 - mx), e1 = expf(m1 - mx);
            float s = e0 + e1;
            g_S[b * 1024 + n]       = e0 / s;
            g_S[b * 1024 + 512 + n] = e1 / s;
        }
    }
}

// ---------------- reorder: g_curves[step][w][ch] -> out[b][ch][n][step] ----------------
__global__ __launch_bounds__(256)
void reorder_kernel(float* __restrict__ out) {
    __shared__ float tile[16][8 * C + 1];
    int b = blockIdx.x >> 5;
    int n0 = (blockIdx.x & 31) * 16;
    int t = threadIdx.x;

    #pragma unroll
    for (int step = 0; step < STEPS; step++) {
        #pragma unroll
        for (int i4 = 0; i4 < 4; i4++) {
            int i = i4 * 4 + (t >> 6);
            int ch = t & 63;
            int w = b * CN + n0 + i;
            tile[i][step * 64 + ch] =
                g_curves[((size_t)step * NW + w) * C + ch];
        }
    }
    __syncthreads();

    int i = t & 15, ch0 = t >> 4;
    #pragma unroll
    for (int cc = 0; cc < 4; cc++) {
        int ch = ch0 + cc * 16;
        float v[8];
        #pragma unroll
        for (int s = 0; s < STEPS; s++) v[s] = tile[i][s * 64 + ch];
        float4* dst = (float4*)(out +
            ((((size_t)b * C + ch) * CN) + n0 + i) * STEPS);
        dst[0] = make_float4(v[0], v[1], v[2], v[3]);
        dst[1] = make_float4(v[4], v[5], v[6], v[7]);
    }
}

extern "C" void kernel_launch(void* const* d_in, const int* in_sizes, int n_in,
                              void* d_out, int out_size) {
    const float* x          = (const float*)d_in[1];
    const int*   adj        = (const int*)  d_in[2];
    const int*   cur        = (const int*)  d_in[3];
    const float* agent_w    = (const float*)d_in[4];
    const float* agent_gamma= (const float*)d_in[5];
    const float* agent_beta = (const float*)d_in[6];
    const float* agent_mean = (const float*)d_in[7];
    const float* agent_var  = (const float*)d_in[8];
    const float* mom_w      = (const float*)d_in[9];
    const float* mom_gamma  = (const float*)d_in[10];
    const float* mom_beta   = (const float*)d_in[11];
    const float* mom_mean   = (const float*)d_in[12];
    const float* mom_var    = (const float*)d_in[13];
    float* out = (float*)d_out;

    dim3 pg(TOT / 16, BN);
    prep_kernel<<<pg, 256>>>(x, agent_w);

    int blocks = NW / 8;   // 1024 blocks of 128 threads (16 lanes/walker)
    walk_step_kernel<true><<<blocks, 128>>>(adj, cur, agent_w, agent_gamma,
        agent_beta, agent_mean, agent_var, mom_w, mom_gamma, mom_beta,
        mom_mean, mom_var, 0);
    for (int s = 1; s < STEPS; s++) {
        walk_step_kernel<false><<<blocks, 128>>>(adj, cur, agent_w, agent_gamma,
            agent_beta, agent_mean, agent_var, mom_w, mom_gamma, mom_beta,
            mom_mean, mom_var, s);
    }
    reorder_kernel<<<BN * (CN / 16), 256>>>(out);
}

// round 10
// speedup vs baseline: 1.3799x; 1.3799x over previous
#include <cuda_runtime.h>
#include <cfloat>

#define TOT 8192
#define BN 16
#define C 64
#define K 20
#define CN 512
#define NW (BN*CN)
#define STEPS 8
#define BN_EPS 1e-5f
#define WSTR 392   // smem floats per walker (42 cols x stride 9, padded: %32==8)

// ---- device scratch (static; no allocations) ----
__device__ float  g_xT[(size_t)BN*TOT*C];        // x transposed (b,node,ch) 32MB
__device__ float2 g_ssq[(size_t)BN*TOT];         // per-node (dot(x,w_lo), |x|^2)
__device__ float  g_curves[(size_t)STEPS*NW*C];  // [step][w][ch] 16MB
__device__ float  g_curf[(size_t)NW*C];
__device__ float  g_pref[(size_t)NW*C];
__device__ int    g_curidx[NW];
__device__ float  g_S[BN*2*CN];                  // softmax exchange

__device__ __forceinline__ float dot4(const float4& a, const float4& b) {
    return a.x*b.x + a.y*b.y + a.z*b.z + a.w*b.w;
}
__device__ __forceinline__ float dot8(const float4& a0, const float4& a1,
                                      const float4& b0, const float4& b1) {
    return dot4(a0,b0) + dot4(a1,b1);
}

// ---------------- fused prep: transpose + per-node (s, |x|^2) (validated R7) ----
__global__ __launch_bounds__(256)
void prep_kernel(const float* __restrict__ x, const float* __restrict__ agent_w) {
    __shared__ float tile[64][33];
    int b = blockIdx.y;
    int node0 = blockIdx.x * 32;
    int t = threadIdx.x;
    int ty = t >> 3;
    int tx = t & 7;

    const float* xb = x + (size_t)b * C * TOT;
    float4 v0 = __ldg((const float4*)(xb + (size_t)ty * TOT + node0) + tx);
    float4 v1 = __ldg((const float4*)(xb + (size_t)(ty + 32) * TOT + node0) + tx);
    tile[ty][tx*4+0] = v0.x; tile[ty][tx*4+1] = v0.y;
    tile[ty][tx*4+2] = v0.z; tile[ty][tx*4+3] = v0.w;
    tile[ty+32][tx*4+0] = v1.x; tile[ty+32][tx*4+1] = v1.y;
    tile[ty+32][tx*4+2] = v1.z; tile[ty+32][tx*4+3] = v1.w;
    __syncthreads();

    int node = t >> 3;
    int j = t & 7;
    float4 a = make_float4(tile[4*j+0][node], tile[4*j+1][node],
                           tile[4*j+2][node], tile[4*j+3][node]);
    float4 c = make_float4(tile[32+4*j+0][node], tile[32+4*j+1][node],
                           tile[32+4*j+2][node], tile[32+4*j+3][node]);
    float4* dst = (float4*)(g_xT + ((size_t)b * TOT + node0 + node) * C);
    dst[j] = a; dst[8 + j] = c;

    const float4* wv = (const float4*)agent_w;
    float4 wA = __ldg(&wv[j]), wB = __ldg(&wv[8 + j]);
    float s = dot4(a, wA) + dot4(c, wB);
    float q = dot4(a, a) + dot4(c, c);
    #pragma unroll
    for (int off = 1; off <= 4; off <<= 1) {
        s += __shfl_xor_sync(0xffffffffu, s, off);
        q += __shfl_xor_sync(0xffffffffu, q, off);
    }
    if (j == 0) g_ssq[(size_t)b * TOT + node0 + node] = make_float2(s, q);
}

// ---------------- one walk step; 8 lanes/walker, 8 walkers/block ----------------
// cols: cvp k -> 9k ; cfp k -> 9(20+k) ; cvcf -> 9*40 ; cf2 -> 9*41
template<bool FIRST>
__global__ __launch_bounds__(64)
void walk_step_kernel(
    const int* __restrict__ adj, const int* __restrict__ cur0,
    const float* __restrict__ agent_w,
    const float* __restrict__ agent_gamma, const float* __restrict__ agent_beta,
    const float* __restrict__ agent_mean,  const float* __restrict__ agent_var,
    const float* __restrict__ mom_w,
    const float* __restrict__ mom_gamma, const float* __restrict__ mom_beta,
    const float* __restrict__ mom_mean,  const float* __restrict__ mom_var,
    int step)
{
    __shared__ float sm[8 * WSTR];
    int sub = threadIdx.x & 7;
    int wi  = threadIdx.x >> 3;
    int w = blockIdx.x * 8 + wi;
    int b = w >> 9;
    int n = w & 511;
    int smb = wi * WSTR;

    const float4* wv = (const float4*)agent_w;
    float4 whA = __ldg(&wv[16 + sub]), whB = __ldg(&wv[24 + sub]);

    float inv_a  = __ldg(agent_gamma) / sqrtf(__ldg(agent_var) + BN_EPS);
    float mean_a = __ldg(agent_mean);
    float beta_a = __ldg(agent_beta);

    const float* xTb = g_xT + (size_t)b * TOT * C;
    const float2* ssqb = g_ssq + (size_t)b * TOT;

    float4 cfA, cfB, pfA, pfB, cvA, cvB;
    int cidx;
    float tpp, n1 = 0.f;

    if (FIRST) {
        cidx = __ldg(&cur0[w]);
        const float4* pv = (const float4*)(xTb + (size_t)cidx * C);
        pfA = __ldg(&pv[sub]); pfB = __ldg(&pv[8 + sub]);
        tpp = dot8(pfA, pfB, whA, whB);
        #pragma unroll
        for (int off = 1; off <= 4; off <<= 1)
            tpp += __shfl_xor_sync(0xffffffffu, tpp, off);
        cfA = make_float4(0.f,0.f,0.f,0.f); cfB = cfA; cvA = cfA; cvB = cfA;
    } else {
        cidx = g_curidx[w];
        const float4* cf = (const float4*)(g_curf + (size_t)w * C);
        cfA = cf[sub]; cfB = cf[8 + sub];
        const float4* pf = (const float4*)(g_pref + (size_t)w * C);
        pfA = pf[sub]; pfB = pf[8 + sub];
        float2 aa = ((const float2*)g_S)[b * 512 + n];
        float a0 = aa.x, a1 = aa.y;
        pfA.x = cfA.x*a0 + pfA.x*a1;  pfA.y = cfA.y*a0 + pfA.y*a1;
        pfA.z = cfA.z*a0 + pfA.z*a1;  pfA.w = cfA.w*a0 + pfA.w*a1;
        pfB.x = cfB.x*a0 + pfB.x*a1;  pfB.y = cfB.y*a0 + pfB.y*a1;
        pfB.z = cfB.z*a0 + pfB.z*a1;  pfB.w = cfB.w*a0 + pfB.w*a1;
        cvA.x = cfA.x - pfA.x; cvA.y = cfA.y - pfA.y;
        cvA.z = cfA.z - pfA.z; cvA.w = cfA.w - pfA.w;
        cvB.x = cfB.x - pfB.x; cvB.y = cfB.y - pfB.y;
        cvB.z = cfB.z - pfB.z; cvB.w = cfB.w - pfB.w;

        float tppp = dot8(pfA, pfB, whA, whB);
        float n1pp = dot8(cvA, cvB, cvA, cvB);
        #pragma unroll
        for (int off = 1; off <= 4; off <<= 1) {
            tppp += __shfl_xor_sync(0xffffffffu, tppp, off);
            n1pp += __shfl_xor_sync(0xffffffffu, n1pp, off);
        }
        tpp = tppp; n1 = sqrtf(n1pp);
    }

    const int* adjp = adj + ((size_t)b * TOT + cidx) * K;
    const int4* adj4 = (const int4*)adjp;

    // ---- lane-owned ssq (hoisted; coalesced adj reads) ----
    int oa0 = __ldg(&adjp[sub]);
    int oa1 = __ldg(&adjp[8 + sub]);
    int oa2 = (sub < 4) ? __ldg(&adjp[16 + sub]) : oa0;
    float2 q0 = __ldg(&ssqb[oa0]);
    float2 q1 = __ldg(&ssqb[oa1]);
    float2 q2 = __ldg(&ssqb[oa2]);

    float best; int ksel;

    if (FIRST) {
        best = (q0.x + tpp - mean_a) * inv_a + beta_a;  ksel = sub;
        float l1 = (q1.x + tpp - mean_a) * inv_a + beta_a;
        if (l1 > best) { best = l1; ksel = 8 + sub; }
        if (sub < 4) {
            float l2 = (q2.x + tpp - mean_a) * inv_a + beta_a;
            if (l2 > best) { best = l2; ksel = 16 + sub; }
        }
    } else {
        // ---- gather 20 rows; STS partials straight to smem (no reg arrays) ----
        #pragma unroll
        for (int q = 0; q < 5; q++) {
            int4 t4 = __ldg(&adj4[q]);
            const float4* p0 = (const float4*)(xTb + (size_t)t4.x * C);
            const float4* p1 = (const float4*)(xTb + (size_t)t4.y * C);
            const float4* p2 = (const float4*)(xTb + (size_t)t4.z * C);
            const float4* p3 = (const float4*)(xTb + (size_t)t4.w * C);
            float4 a0 = __ldg(&p0[sub]), b0 = __ldg(&p0[8+sub]);
            float4 a1 = __ldg(&p1[sub]), b1 = __ldg(&p1[8+sub]);
            float4 a2 = __ldg(&p2[sub]), b2 = __ldg(&p2[8+sub]);
            float4 a3 = __ldg(&p3[sub]), b3 = __ldg(&p3[8+sub]);
            sm[smb + 9*(4*q+0) + sub] = dot8(cvA, cvB, a0, b0);
            sm[smb + 9*(4*q+1) + sub] = dot8(cvA, cvB, a1, b1);
            sm[smb + 9*(4*q+2) + sub] = dot8(cvA, cvB, a2, b2);
            sm[smb + 9*(4*q+3) + sub] = dot8(cvA, cvB, a3, b3);
            sm[smb + 9*(20+4*q+0) + sub] = dot8(cfA, cfB, a0, b0);
            sm[smb + 9*(20+4*q+1) + sub] = dot8(cfA, cfB, a1, b1);
            sm[smb + 9*(20+4*q+2) + sub] = dot8(cfA, cfB, a2, b2);
            sm[smb + 9*(20+4*q+3) + sub] = dot8(cfA, cfB, a3, b3);
        }
        // cvcf / cf2 partials through the SAME path (tree congruence -> cc==0 on p==cf)
        sm[smb + 9*40 + sub] = dot8(cvA, cvB, cfA, cfB);
        sm[smb + 9*41 + sub] = dot8(cfA, cfB, cfA, cfB);
        __syncwarp();

        // ---- serial column sums, fixed order i=0..7 (same tree for all cols) ----
        int c2 = (sub < 4) ? (16 + sub) : ((sub == 4) ? 40 : 41);
        int c5 = (sub < 4) ? (36 + sub) : 41;
        float S0=0.f,S1=0.f,S2=0.f,T0=0.f,T1=0.f,T2=0.f;
        #pragma unroll
        for (int i = 0; i < 8; i++) {
            S0 += sm[smb + 9*sub + i];
            S1 += sm[smb + 9*(8+sub) + i];
            S2 += sm[smb + 9*c2 + i];
            T0 += sm[smb + 9*(20+sub) + i];
            T1 += sm[smb + 9*(28+sub) + i];
            T2 += sm[smb + 9*c5 + i];
        }
        float cvcf = __shfl_sync(0xffffffffu, S2, 4, 8);   // lane 4's col-40 sum
        float cf2  = __shfl_sync(0xffffffffu, S2, 5, 8);   // lane 5's col-41 sum

        // ---- lane-distributed epilogue (2-3 candidates per lane) ----
        {
            float lg = (q0.x + tpp - mean_a) * inv_a + beta_a;
            float cc = S0 - cvcf;
            float nn = q0.y - 2.f * T0 + cf2;
            float cosv = cc / fmaxf(n1 * sqrtf(nn), 1e-8f);
            lg *= fminf(fmaxf(1.f + cosv, 0.f), 1.f);
            best = lg; ksel = sub;
        }
        {
            float lg = (q1.x + tpp - mean_a) * inv_a + beta_a;
            float cc = S1 - cvcf;
            float nn = q1.y - 2.f * T1 + cf2;
            float cosv = cc / fmaxf(n1 * sqrtf(nn), 1e-8f);
            lg *= fminf(fmaxf(1.f + cosv, 0.f), 1.f);
            if (lg > best) { best = lg; ksel = 8 + sub; }
        }
        if (sub < 4) {
            float lg = (q2.x + tpp - mean_a) * inv_a + beta_a;
            float cc = S2 - cvcf;
            float nn = q2.y - 2.f * T2 + cf2;
            float cosv = cc / fmaxf(n1 * sqrtf(nn), 1e-8f);
            lg *= fminf(fmaxf(1.f + cosv, 0.f), 1.f);
            if (lg > best) { best = lg; ksel = 16 + sub; }
        }
    }

    // ---- argmax combine over 8 lanes (ties -> smallest k = first max; R5-validated) ----
    #pragma unroll
    for (int off = 1; off <= 4; off <<= 1) {
        float ob = __shfl_xor_sync(0xffffffffu, best, off);
        int   ok = __shfl_xor_sync(0xffffffffu, ksel, off);
        if (ob > best || (ob == best && ok < ksel)) { best = ob; ksel = ok; }
    }

    int nidx = __ldg(&adjp[ksel]);
    {
        const float4* pv = (const float4*)(xTb + (size_t)nidx * C);
        cfA = __ldg(&pv[sub]); cfB = __ldg(&pv[8 + sub]);
    }

    // ---- coalesced curve store + persist state ----
    {
        float4* cvo = (float4*)(g_curves + ((size_t)step * NW + w) * C);
        cvo[sub] = cfA; cvo[8 + sub] = cfB;
        float4* cfo = (float4*)(g_curf + (size_t)w * C);
        cfo[sub] = cfA; cfo[8 + sub] = cfB;
        float4* pfo = (float4*)(g_pref + (size_t)w * C);
        pfo[sub] = pfA; pfo[8 + sub] = pfB;
        if (sub == 0) g_curidx[w] = nidx;
    }

    if (step < STEPS - 1) {
        const float4* mv = (const float4*)mom_w;
        float l0 = dot8(cfA, cfB, __ldg(&mv[sub]),      __ldg(&mv[8 + sub]))
                 + dot8(pfA, pfB, __ldg(&mv[16 + sub]), __ldg(&mv[24 + sub]));
        float l1 = dot8(cfA, cfB, __ldg(&mv[32 + sub]), __ldg(&mv[40 + sub]))
                 + dot8(pfA, pfB, __ldg(&mv[48 + sub]), __ldg(&mv[56 + sub]));
        #pragma unroll
        for (int off = 1; off <= 4; off <<= 1) {
            l0 += __shfl_xor_sync(0xffffffffu, l0, off);
            l1 += __shfl_xor_sync(0xffffffffu, l1, off);
        }
        if (sub == 0) {
            float inv0 = __ldg(&mom_gamma[0]) / sqrtf(__ldg(&mom_var[0]) + BN_EPS);
            float inv1 = __ldg(&mom_gamma[1]) / sqrtf(__ldg(&mom_var[1]) + BN_EPS);
            float m0 = (l0 - __ldg(&mom_mean[0])) * inv0 + __ldg(&mom_beta[0]);
            float m1 = (l1 - __ldg(&mom_mean[1])) * inv1 + __ldg(&mom_beta[1]);
            float mx = fmaxf(m0, m1);
            float e0 = expf(m0 - mx), e1 = expf(m1 - mx);
            float s = e0 + e1;
            g_S[b * 1024 + n]       = e0 / s;
            g_S[b * 1024 + 512 + n] = e1 / s;
        }
    }
}

// ---------------- reorder: g_curves[step][w][ch] -> out[b][ch][n][step] ----------------
__global__ __launch_bounds__(256)
void reorder_kernel(float* __restrict__ out) {
    __shared__ float tile[16][8 * C + 1];
    int b = blockIdx.x >> 5;
    int n0 = (blockIdx.x & 31) * 16;
    int t = threadIdx.x;

    #pragma unroll
    for (int step = 0; step < STEPS; step++) {
        #pragma unroll
        for (int i4 = 0; i4 < 4; i4++) {
            int i = i4 * 4 + (t >> 6);
            int ch = t & 63;
            int w = b * CN + n0 + i;
            tile[i][step * 64 + ch] =
                g_curves[((size_t)step * NW + w) * C + ch];
        }
    }
    __syncthreads();

    int i = t & 15, ch0 = t >> 4;
    #pragma unroll
    for (int cc = 0; cc < 4; cc++) {
        int ch = ch0 + cc * 16;
        float v[8];
        #pragma unroll
        for (int s = 0; s < STEPS; s++) v[s] = tile[i][s * 64 + ch];
        float4* dst = (float4*)(out +
            ((((size_t)b * C + ch) * CN) + n0 + i) * STEPS);
        dst[0] = make_float4(v[0], v[1], v[2], v[3]);
        dst[1] = make_float4(v[4], v[5], v[6], v[7]);
    }
}

extern "C" void kernel_launch(void* const* d_in, const int* in_sizes, int n_in,
                              void* d_out, int out_size) {
    const float* x          = (const float*)d_in[1];
    const int*   adj        = (const int*)  d_in[2];
    const int*   cur        = (const int*)  d_in[3];
    const float* agent_w    = (const float*)d_in[4];
    const float* agent_gamma= (const float*)d_in[5];
    const float* agent_beta = (const float*)d_in[6];
    const float* agent_mean = (const float*)d_in[7];
    const float* agent_var  = (const float*)d_in[8];
    const float* mom_w      = (const float*)d_in[9];
    const float* mom_gamma  = (const float*)d_in[10];
    const float* mom_beta   = (const float*)d_in[11];
    const float* mom_mean   = (const float*)d_in[12];
    const float* mom_var    = (const float*)d_in[13];
    float* out = (float*)d_out;

    dim3 pg(TOT / 32, BN);
    prep_kernel<<<pg, 256>>>(x, agent_w);

    int blocks = NW / 8;   // 1024 blocks of 64 threads
    walk_step_kernel<true><<<blocks, 64>>>(adj, cur, agent_w, agent_gamma,
        agent_beta, agent_mean, agent_var, mom_w, mom_gamma, mom_beta,
        mom_mean, mom_var, 0);
    for (int s = 1; s < STEPS; s++) {
        walk_step_kernel<false><<<blocks, 64>>>(adj, cur, agent_w, agent_gamma,
            agent_beta, agent_mean, agent_var, mom_w, mom_gamma, mom_beta,
            mom_mean, mom_var, s);
    }
    reorder_kernel<<<BN * (CN / 16), 256>>>(out);
}

// round 11
// speedup vs baseline: 1.4145x; 1.0250x over previous
#include <cuda_runtime.h>
#include <cfloat>

#define TOT 8192
#define BN 16
#define C 64
#define K 20
#define CN 512
#define NW (BN*CN)
#define STEPS 8
#define NBLK 1024
#define BN_EPS 1e-5f
#define WSTR 200   // smem floats per walker: 22 cols x stride 9 = 198, pad->200 (200%32==8)

// ---- device scratch (static; no allocations) ----
__device__ float  g_xT[(size_t)BN*TOT*C];        // x transposed (b,node,ch) 32MB
__device__ float2 g_ssq[(size_t)BN*TOT];         // per-node (dot(x,w_lo), |x|^2)
__device__ float  g_curves[(size_t)STEPS*NW*C];  // [step][w][ch] 16MB
__device__ float  g_S[2][BN*2*CN];               // double-buffered softmax exchange
__device__ unsigned g_bar;                       // grid barrier counter

__device__ __forceinline__ float dot4(const float4& a, const float4& b) {
    return a.x*b.x + a.y*b.y + a.z*b.z + a.w*b.w;
}
__device__ __forceinline__ float dot8(const float4& a0, const float4& a1,
                                      const float4& b0, const float4& b1) {
    return dot4(a0,b0) + dot4(a1,b1);
}

// ---------------- fused prep: transpose + per-node (s, |x|^2) ----------------
__global__ __launch_bounds__(256)
void prep_kernel(const float* __restrict__ x, const float* __restrict__ agent_w) {
    __shared__ float tile[64][33];
    int b = blockIdx.y;
    int node0 = blockIdx.x * 32;
    int t = threadIdx.x;
    int ty = t >> 3;
    int tx = t & 7;

    const float* xb = x + (size_t)b * C * TOT;
    float4 v0 = __ldg((const float4*)(xb + (size_t)ty * TOT + node0) + tx);
    float4 v1 = __ldg((const float4*)(xb + (size_t)(ty + 32) * TOT + node0) + tx);
    tile[ty][tx*4+0] = v0.x; tile[ty][tx*4+1] = v0.y;
    tile[ty][tx*4+2] = v0.z; tile[ty][tx*4+3] = v0.w;
    tile[ty+32][tx*4+0] = v1.x; tile[ty+32][tx*4+1] = v1.y;
    tile[ty+32][tx*4+2] = v1.z; tile[ty+32][tx*4+3] = v1.w;
    __syncthreads();

    int node = t >> 3;
    int j = t & 7;
    float4 a = make_float4(tile[4*j+0][node], tile[4*j+1][node],
                           tile[4*j+2][node], tile[4*j+3][node]);
    float4 c = make_float4(tile[32+4*j+0][node], tile[32+4*j+1][node],
                           tile[32+4*j+2][node], tile[32+4*j+3][node]);
    float4* dst = (float4*)(g_xT + ((size_t)b * TOT + node0 + node) * C);
    dst[j] = a; dst[8 + j] = c;

    const float4* wv = (const float4*)agent_w;
    float4 wA = __ldg(&wv[j]), wB = __ldg(&wv[8 + j]);
    float s = dot4(a, wA) + dot4(c, wB);
    float q = dot4(a, a) + dot4(c, c);
    #pragma unroll
    for (int off = 1; off <= 4; off <<= 1) {
        s += __shfl_xor_sync(0xffffffffu, s, off);
        q += __shfl_xor_sync(0xffffffffu, q, off);
    }
    if (j == 0) g_ssq[(size_t)b * TOT + node0 + node] = make_float2(s, q);
}

// ---------------- persistent walk: all 8 steps; 8 lanes/walker, 8 walkers/block ----
// smem cols: phase A: cvp k->col k (0..19), cvcf->20, cf2->21 ; phase B: cfp k->col k
__global__ __launch_bounds__(64, 8)
void walk_persistent(
    const int* __restrict__ adj, const int* __restrict__ cur0,
    const float* __restrict__ agent_w,
    const float* __restrict__ agent_gamma, const float* __restrict__ agent_beta,
    const float* __restrict__ agent_mean,  const float* __restrict__ agent_var,
    const float* __restrict__ mom_w,
    const float* __restrict__ mom_gamma, const float* __restrict__ mom_beta,
    const float* __restrict__ mom_mean,  const float* __restrict__ mom_var)
{
    __shared__ float sm[8 * WSTR];
    int sub = threadIdx.x & 7;
    int wi  = threadIdx.x >> 3;
    int w = blockIdx.x * 8 + wi;
    int b = w >> 9;
    int n = w & 511;
    int smb = wi * WSTR;

    const float4* wv = (const float4*)agent_w;
    float4 whA = __ldg(&wv[16 + sub]), whB = __ldg(&wv[24 + sub]);

    float inv_a  = __ldg(agent_gamma) / sqrtf(__ldg(agent_var) + BN_EPS);
    float mean_a = __ldg(agent_mean);
    float beta_a = __ldg(agent_beta);

    const float* xTb = g_xT + (size_t)b * TOT * C;
    const float2* ssqb = g_ssq + (size_t)b * TOT;

    int cidx = __ldg(&cur0[w]);
    float4 cfA = make_float4(0.f,0.f,0.f,0.f), cfB = cfA;
    float4 pfA = cfA, pfB = cfA;

    for (int step = 0; step < STEPS; step++) {
        float4 cvA, cvB;
        float tpp, n1 = 0.f;

        if (step == 0) {
            const float4* pv = (const float4*)(xTb + (size_t)cidx * C);
            pfA = __ldg(&pv[sub]); pfB = __ldg(&pv[8 + sub]);
            tpp = dot8(pfA, pfB, whA, whB);
            #pragma unroll
            for (int off = 1; off <= 4; off <<= 1)
                tpp += __shfl_xor_sync(0xffffffffu, tpp, off);
            cvA = make_float4(0.f,0.f,0.f,0.f); cvB = cvA;
        } else {
            float2 aa = __ldcg(((const float2*)g_S[(step - 1) & 1]) + b * 512 + n);
            float a0 = aa.x, a1 = aa.y;
            pfA.x = cfA.x*a0 + pfA.x*a1;  pfA.y = cfA.y*a0 + pfA.y*a1;
            pfA.z = cfA.z*a0 + pfA.z*a1;  pfA.w = cfA.w*a0 + pfA.w*a1;
            pfB.x = cfB.x*a0 + pfB.x*a1;  pfB.y = cfB.y*a0 + pfB.y*a1;
            pfB.z = cfB.z*a0 + pfB.z*a1;  pfB.w = cfB.w*a0 + pfB.w*a1;
            cvA.x = cfA.x - pfA.x; cvA.y = cfA.y - pfA.y;
            cvA.z = cfA.z - pfA.z; cvA.w = cfA.w - pfA.w;
            cvB.x = cfB.x - pfB.x; cvB.y = cfB.y - pfB.y;
            cvB.z = cfB.z - pfB.z; cvB.w = cfB.w - pfB.w;

            float tppp = dot8(pfA, pfB, whA, whB);
            float n1pp = dot8(cvA, cvB, cvA, cvB);
            #pragma unroll
            for (int off = 1; off <= 4; off <<= 1) {
                tppp += __shfl_xor_sync(0xffffffffu, tppp, off);
                n1pp += __shfl_xor_sync(0xffffffffu, n1pp, off);
            }
            tpp = tppp; n1 = sqrtf(n1pp);
        }

        const int* adjp = adj + ((size_t)b * TOT + cidx) * K;
        const int4* adj4 = (const int4*)adjp;

        // ---- lane-owned ssq (hoisted; coalesced adj reads) ----
        int oa0 = __ldg(&adjp[sub]);
        int oa1 = __ldg(&adjp[8 + sub]);
        int oa2 = (sub < 4) ? __ldg(&adjp[16 + sub]) : oa0;
        float2 q0 = __ldg(&ssqb[oa0]);
        float2 q1 = __ldg(&ssqb[oa1]);
        float2 q2 = __ldg(&ssqb[oa2]);

        float best; int ksel;

        if (step == 0) {
            best = (q0.x + tpp - mean_a) * inv_a + beta_a;  ksel = sub;
            float l1 = (q1.x + tpp - mean_a) * inv_a + beta_a;
            if (l1 > best) { best = l1; ksel = 8 + sub; }
            if (sub < 4) {
                float l2 = (q2.x + tpp - mean_a) * inv_a + beta_a;
                if (l2 > best) { best = l2; ksel = 16 + sub; }
            }
        } else {
            // ---- gather 20 rows; STS cvp partials; cfp partials in regs ----
            float cfp[K];
            #pragma unroll
            for (int q = 0; q < 5; q++) {
                int4 t4 = __ldg(&adj4[q]);
                const float4* p0 = (const float4*)(xTb + (size_t)t4.x * C);
                const float4* p1 = (const float4*)(xTb + (size_t)t4.y * C);
                const float4* p2 = (const float4*)(xTb + (size_t)t4.z * C);
                const float4* p3 = (const float4*)(xTb + (size_t)t4.w * C);
                float4 a0 = __ldg(&p0[sub]), b0 = __ldg(&p0[8+sub]);
                float4 a1 = __ldg(&p1[sub]), b1 = __ldg(&p1[8+sub]);
                float4 a2 = __ldg(&p2[sub]), b2 = __ldg(&p2[8+sub]);
                float4 a3 = __ldg(&p3[sub]), b3 = __ldg(&p3[8+sub]);
                sm[smb + 9*(4*q+0) + sub] = dot8(cvA, cvB, a0, b0);
                sm[smb + 9*(4*q+1) + sub] = dot8(cvA, cvB, a1, b1);
                sm[smb + 9*(4*q+2) + sub] = dot8(cvA, cvB, a2, b2);
                sm[smb + 9*(4*q+3) + sub] = dot8(cvA, cvB, a3, b3);
                cfp[4*q+0] = dot8(cfA, cfB, a0, b0);
                cfp[4*q+1] = dot8(cfA, cfB, a1, b1);
                cfp[4*q+2] = dot8(cfA, cfB, a2, b2);
                cfp[4*q+3] = dot8(cfA, cfB, a3, b3);
            }
            // cvcf / cf2 through the SAME path (tree congruence -> cc==0 on p==cf)
            sm[smb + 9*20 + sub] = dot8(cvA, cvB, cfA, cfB);
            sm[smb + 9*21 + sub] = dot8(cfA, cfB, cfA, cfB);
            __syncwarp();

            // ---- phase A: serial column sums (fixed order i=0..7) for cv side ----
            int c2 = (sub < 4) ? (16 + sub) : ((sub == 4) ? 20 : 21);
            float S0=0.f, S1=0.f, S2=0.f;
            #pragma unroll
            for (int i = 0; i < 8; i++) {
                S0 += sm[smb + 9*sub + i];
                S1 += sm[smb + 9*(8+sub) + i];
                S2 += sm[smb + 9*c2 + i];
            }
            float cvcf = __shfl_sync(0xffffffffu, S2, 4, 8);
            float cf2  = __shfl_sync(0xffffffffu, S2, 5, 8);
            __syncwarp();   // phase A reads done before overwrite

            // ---- phase B: store cfp partials (constant cols), reduce ----
            #pragma unroll
            for (int k = 0; k < K; k++) sm[smb + 9*k + sub] = cfp[k];
            __syncwarp();
            int c5 = (sub < 4) ? (16 + sub) : 0;
            float T0=0.f, T1=0.f, T2=0.f;
            #pragma unroll
            for (int i = 0; i < 8; i++) {
                T0 += sm[smb + 9*sub + i];
                T1 += sm[smb + 9*(8+sub) + i];
                T2 += sm[smb + 9*c5 + i];
            }

            // ---- lane-distributed epilogue (2-3 candidates per lane) ----
            {
                float lg = (q0.x + tpp - mean_a) * inv_a + beta_a;
                float cc = S0 - cvcf;
                float nn = q0.y - 2.f * T0 + cf2;
                float cosv = cc / fmaxf(n1 * sqrtf(nn), 1e-8f);
                lg *= fminf(fmaxf(1.f + cosv, 0.f), 1.f);
                best = lg; ksel = sub;
            }
            {
                float lg = (q1.x + tpp - mean_a) * inv_a + beta_a;
                float cc = S1 - cvcf;
                float nn = q1.y - 2.f * T1 + cf2;
                float cosv = cc / fmaxf(n1 * sqrtf(nn), 1e-8f);
                lg *= fminf(fmaxf(1.f + cosv, 0.f), 1.f);
                if (lg > best) { best = lg; ksel = 8 + sub; }
            }
            if (sub < 4) {
                float lg = (q2.x + tpp - mean_a) * inv_a + beta_a;
                float cc = S2 - cvcf;
                float nn = q2.y - 2.f * T2 + cf2;
                float cosv = cc / fmaxf(n1 * sqrtf(nn), 1e-8f);
                lg *= fminf(fmaxf(1.f + cosv, 0.f), 1.f);
                if (lg > best) { best = lg; ksel = 16 + sub; }
            }
        }

        // ---- argmax combine over 8 lanes (ties -> smallest k = first max) ----
        #pragma unroll
        for (int off = 1; off <= 4; off <<= 1) {
            float ob = __shfl_xor_sync(0xffffffffu, best, off);
            int   ok = __shfl_xor_sync(0xffffffffu, ksel, off);
            if (ob > best || (ob == best && ok < ksel)) { best = ob; ksel = ok; }
        }

        int nidx = __ldg(&adjp[ksel]);
        {
            const float4* pv = (const float4*)(xTb + (size_t)nidx * C);
            cfA = __ldg(&pv[sub]); cfB = __ldg(&pv[8 + sub]);
        }
        cidx = nidx;

        // ---- coalesced curve store (state stays in registers) ----
        {
            float4* cvo = (float4*)(g_curves + ((size_t)step * NW + w) * C);
            cvo[sub] = cfA; cvo[8 + sub] = cfB;
        }

        if (step < STEPS - 1) {
            const float4* mv = (const float4*)mom_w;
            float l0 = dot8(cfA, cfB, __ldg(&mv[sub]),      __ldg(&mv[8 + sub]))
                     + dot8(pfA, pfB, __ldg(&mv[16 + sub]), __ldg(&mv[24 + sub]));
            float l1 = dot8(cfA, cfB, __ldg(&mv[32 + sub]), __ldg(&mv[40 + sub]))
                     + dot8(pfA, pfB, __ldg(&mv[48 + sub]), __ldg(&mv[56 + sub]));
            #pragma unroll
            for (int off = 1; off <= 4; off <<= 1) {
                l0 += __shfl_xor_sync(0xffffffffu, l0, off);
                l1 += __shfl_xor_sync(0xffffffffu, l1, off);
            }
            if (sub == 0) {
                float inv0 = __ldg(&mom_gamma[0]) / sqrtf(__ldg(&mom_var[0]) + BN_EPS);
                float inv1 = __ldg(&mom_gamma[1]) / sqrtf(__ldg(&mom_var[1]) + BN_EPS);
                float m0 = (l0 - __ldg(&mom_mean[0])) * inv0 + __ldg(&mom_beta[0]);
                float m1 = (l1 - __ldg(&mom_mean[1])) * inv1 + __ldg(&mom_beta[1]);
                float mx = fmaxf(m0, m1);
                float e0 = expf(m0 - mx), e1 = expf(m1 - mx);
                float s = e0 + e1;
                g_S[step & 1][b * 1024 + n]       = e0 / s;
                g_S[step & 1][b * 1024 + 512 + n] = e1 / s;
            }
            // ---- grid barrier (all 1024 blocks resident: 8/SM x 148 = 1184 slots) ----
            __threadfence();
            __syncthreads();
            if (threadIdx.x == 0) {
                atomicAdd(&g_bar, 1u);
                unsigned target = (unsigned)(step + 1) * NBLK;
                while (*((volatile unsigned*)&g_bar) < target) { }
            }
            __syncthreads();
        }
    }
}

// ---------------- reorder: g_curves[step][w][ch] -> out[b][ch][n][step] ----------------
__global__ __launch_bounds__(256)
void reorder_kernel(float* __restrict__ out) {
    __shared__ float tile[16][8 * C + 1];
    int b = blockIdx.x >> 5;
    int n0 = (blockIdx.x & 31) * 16;
    int t = threadIdx.x;

    #pragma unroll
    for (int step = 0; step < STEPS; step++) {
        #pragma unroll
        for (int i4 = 0; i4 < 4; i4++) {
            int i = i4 * 4 + (t >> 6);
            int ch = t & 63;
            int w = b * CN + n0 + i;
            tile[i][step * 64 + ch] =
                g_curves[((size_t)step * NW + w) * C + ch];
        }
    }
    __syncthreads();

    int i = t & 15, ch0 = t >> 4;
    #pragma unroll
    for (int cc = 0; cc < 4; cc++) {
        int ch = ch0 + cc * 16;
        float v[8];
        #pragma unroll
        for (int s = 0; s < STEPS; s++) v[s] = tile[i][s * 64 + ch];
        float4* dst = (float4*)(out +
            ((((size_t)b * C + ch) * CN) + n0 + i) * STEPS);
        dst[0] = make_float4(v[0], v[1], v[2], v[3]);
        dst[1] = make_float4(v[4], v[5], v[6], v[7]);
    }
}

extern "C" void kernel_launch(void* const* d_in, const int* in_sizes, int n_in,
                              void* d_out, int out_size) {
    const float* x          = (const float*)d_in[1];
    const int*   adj        = (const int*)  d_in[2];
    const int*   cur        = (const int*)  d_in[3];
    const float* agent_w    = (const float*)d_in[4];
    const float* agent_gamma= (const float*)d_in[5];
    const float* agent_beta = (const float*)d_in[6];
    const float* agent_mean = (const float*)d_in[7];
    const float* agent_var  = (const float*)d_in[8];
    const float* mom_w      = (const float*)d_in[9];
    const float* mom_gamma  = (const float*)d_in[10];
    const float* mom_beta   = (const float*)d_in[11];
    const float* mom_mean   = (const float*)d_in[12];
    const float* mom_var    = (const float*)d_in[13];
    float* out = (float*)d_out;

    // reset grid-barrier counter (memset node is graph-capturable)
    void* bar_addr = nullptr;
    cudaGetSymbolAddress(&bar_addr, g_bar);
    cudaMemsetAsync(bar_addr, 0, sizeof(unsigned));

    dim3 pg(TOT / 32, BN);
    prep_kernel<<<pg, 256>>>(x, agent_w);

    walk_persistent<<<NBLK, 64>>>(adj, cur, agent_w, agent_gamma, agent_beta,
        agent_mean, agent_var, mom_w, mom_gamma, mom_beta, mom_mean, mom_var);

    reorder_kernel<<<BN * (CN / 16), 256>>>(out);
}

// round 12
// speedup vs baseline: 1.4748x; 1.0427x over previous
#include <cuda_runtime.h>
#include <cfloat>

#define TOT 8192
#define BN 16
#define C 64
#define K 20
#define CN 512
#define NW (BN*CN)
#define STEPS 8
#define BN_EPS 1e-5f
#define WSTR 400   // smem floats per walker: 22 cols x stride 17 = 374, pad->400 (400%32==16)

// ---- device scratch (static; no allocations) ----
__device__ float  g_xT[(size_t)BN*TOT*C];        // x transposed (b,node,ch) 32MB
__device__ float2 g_ssq[(size_t)BN*TOT];         // per-node (dot(x,w_lo), |x|^2)
__device__ float  g_curves[(size_t)STEPS*NW*C];  // [step][w][ch] 16MB
__device__ float  g_curf[(size_t)NW*C];
__device__ float  g_pref[(size_t)NW*C];
__device__ int    g_curidx[NW];
__device__ float  g_S[BN*2*CN];                  // softmax exchange

__device__ __forceinline__ float dot4(const float4& a, const float4& b) {
    return a.x*b.x + a.y*b.y + a.z*b.z + a.w*b.w;
}

// ---------------- fused prep: transpose + per-node (s, |x|^2) (validated) ----
__global__ __launch_bounds__(256)
void prep_kernel(const float* __restrict__ x, const float* __restrict__ agent_w) {
    __shared__ float tile[64][33];
    int b = blockIdx.y;
    int node0 = blockIdx.x * 32;
    int t = threadIdx.x;
    int ty = t >> 3;
    int tx = t & 7;

    const float* xb = x + (size_t)b * C * TOT;
    float4 v0 = __ldg((const float4*)(xb + (size_t)ty * TOT + node0) + tx);
    float4 v1 = __ldg((const float4*)(xb + (size_t)(ty + 32) * TOT + node0) + tx);
    tile[ty][tx*4+0] = v0.x; tile[ty][tx*4+1] = v0.y;
    tile[ty][tx*4+2] = v0.z; tile[ty][tx*4+3] = v0.w;
    tile[ty+32][tx*4+0] = v1.x; tile[ty+32][tx*4+1] = v1.y;
    tile[ty+32][tx*4+2] = v1.z; tile[ty+32][tx*4+3] = v1.w;
    __syncthreads();

    int node = t >> 3;
    int j = t & 7;
    float4 a = make_float4(tile[4*j+0][node], tile[4*j+1][node],
                           tile[4*j+2][node], tile[4*j+3][node]);
    float4 c = make_float4(tile[32+4*j+0][node], tile[32+4*j+1][node],
                           tile[32+4*j+2][node], tile[32+4*j+3][node]);
    float4* dst = (float4*)(g_xT + ((size_t)b * TOT + node0 + node) * C);
    dst[j] = a; dst[8 + j] = c;

    const float4* wv = (const float4*)agent_w;
    float4 wA = __ldg(&wv[j]), wB = __ldg(&wv[8 + j]);
    float s = dot4(a, wA) + dot4(c, wB);
    float q = dot4(a, a) + dot4(c, c);
    #pragma unroll
    for (int off = 1; off <= 4; off <<= 1) {
        s += __shfl_xor_sync(0xffffffffu, s, off);
        q += __shfl_xor_sync(0xffffffffu, q, off);
    }
    if (j == 0) g_ssq[(size_t)b * TOT + node0 + node] = make_float2(s, q);
}

// ---------------- one walk step; 16 lanes/walker, 8 walkers/block ----------------
// lane sub (0..15) owns channels [4*sub..4*sub+3].
// smem cols (stride 17): phase A: cvp k->col k (0..19), cvcf->20, cf2->21;
//                        phase B: cfp k->col k.
template<bool FIRST>
__global__ __launch_bounds__(128)
void walk_step_kernel(
    const int* __restrict__ adj, const int* __restrict__ cur0,
    const float* __restrict__ agent_w,
    const float* __restrict__ agent_gamma, const float* __restrict__ agent_beta,
    const float* __restrict__ agent_mean,  const float* __restrict__ agent_var,
    const float* __restrict__ mom_w,
    const float* __restrict__ mom_gamma, const float* __restrict__ mom_beta,
    const float* __restrict__ mom_mean,  const float* __restrict__ mom_var,
    int step)
{
    __shared__ float sm[8 * WSTR];
    int sub = threadIdx.x & 15;
    int wi  = threadIdx.x >> 4;
    int w = blockIdx.x * 8 + wi;
    int b = w >> 9;
    int n = w & 511;
    int smb = wi * WSTR;

    const float4* wv = (const float4*)agent_w;
    float4 wh = __ldg(&wv[16 + sub]);              // agent_w[64:128]

    float inv_a  = __ldg(agent_gamma) / sqrtf(__ldg(agent_var) + BN_EPS);
    float mean_a = __ldg(agent_mean);
    float beta_a = __ldg(agent_beta);

    const float* xTb = g_xT + (size_t)b * TOT * C;
    const float2* ssqb = g_ssq + (size_t)b * TOT;

    float4 cf4, pf4, cv4;
    int cidx;
    float tpp, n1 = 0.f;

    if (FIRST) {
        cidx = __ldg(&cur0[w]);
        pf4 = __ldg(&((const float4*)(xTb + (size_t)cidx * C))[sub]);
        tpp = dot4(pf4, wh);
        #pragma unroll
        for (int off = 1; off <= 8; off <<= 1)
            tpp += __shfl_xor_sync(0xffffffffu, tpp, off);
        cf4 = make_float4(0.f,0.f,0.f,0.f); cv4 = cf4;
    } else {
        cidx = g_curidx[w];
        cf4 = ((const float4*)(g_curf + (size_t)w * C))[sub];
        pf4 = ((const float4*)(g_pref + (size_t)w * C))[sub];
        float2 aa = ((const float2*)g_S)[b * 512 + n];   // entries 2n, 2n+1
        float a0 = aa.x, a1 = aa.y;
        pf4.x = cf4.x*a0 + pf4.x*a1;  pf4.y = cf4.y*a0 + pf4.y*a1;
        pf4.z = cf4.z*a0 + pf4.z*a1;  pf4.w = cf4.w*a0 + pf4.w*a1;
        cv4.x = cf4.x - pf4.x; cv4.y = cf4.y - pf4.y;
        cv4.z = cf4.z - pf4.z; cv4.w = cf4.w - pf4.w;

        float tppp = dot4(pf4, wh);
        float n1pp = dot4(cv4, cv4);
        #pragma unroll
        for (int off = 1; off <= 8; off <<= 1) {
            tppp += __shfl_xor_sync(0xffffffffu, tppp, off);
            n1pp += __shfl_xor_sync(0xffffffffu, n1pp, off);
        }
        tpp = tppp; n1 = sqrtf(n1pp);
    }

    const int* adjp = adj + ((size_t)b * TOT + cidx) * K;
    const int4* adj4 = (const int4*)adjp;

    // ---- lane-owned ssq loads (coalesced adj reads; hoisted) ----
    int oa0 = __ldg(&adjp[sub]);
    int oa1 = (sub < 4) ? __ldg(&adjp[16 + sub]) : oa0;
    float2 q0 = __ldg(&ssqb[oa0]);
    float2 q1 = __ldg(&ssqb[oa1]);

    float best; int ksel;

    if (FIRST) {
        best = (q0.x + tpp - mean_a) * inv_a + beta_a;  ksel = sub;
        if (sub < 4) {
            float l1 = (q1.x + tpp - mean_a) * inv_a + beta_a;
            if (l1 > best) { best = l1; ksel = 16 + sub; }
        }
    } else {
        // ---- gather 20 rows (256B coalesced each, full MLP) ----
        float cfp[K];
        #pragma unroll
        for (int q = 0; q < 5; q++) {
            int4 t4 = __ldg(&adj4[q]);
            float4 p0 = __ldg(&((const float4*)(xTb + (size_t)t4.x * C))[sub]);
            float4 p1 = __ldg(&((const float4*)(xTb + (size_t)t4.y * C))[sub]);
            float4 p2 = __ldg(&((const float4*)(xTb + (size_t)t4.z * C))[sub]);
            float4 p3 = __ldg(&((const float4*)(xTb + (size_t)t4.w * C))[sub]);
            sm[smb + 17*(4*q+0) + sub] = dot4(cv4, p0);
            sm[smb + 17*(4*q+1) + sub] = dot4(cv4, p1);
            sm[smb + 17*(4*q+2) + sub] = dot4(cv4, p2);
            sm[smb + 17*(4*q+3) + sub] = dot4(cv4, p3);
            cfp[4*q+0] = dot4(cf4, p0);
            cfp[4*q+1] = dot4(cf4, p1);
            cfp[4*q+2] = dot4(cf4, p2);
            cfp[4*q+3] = dot4(cf4, p3);
        }
        // cvcf / cf2 through SAME tree (=> cc exactly 0 on self-neighbors)
        sm[smb + 17*20 + sub] = dot4(cv4, cf4);
        sm[smb + 17*21 + sub] = dot4(cf4, cf4);
        __syncwarp();

        // ---- phase A: 16-way serial column sums (fixed order) for cv side ----
        int cS1 = (sub < 6) ? (16 + sub) : sub;
        float S0 = 0.f, S1 = 0.f;
        #pragma unroll
        for (int i = 0; i < 16; i++) {
            S0 += sm[smb + 17*sub + i];
            S1 += sm[smb + 17*cS1 + i];
        }
        float cvcf = __shfl_sync(0xffffffffu, S1, 4, 16);  // lane 4 owns col 20
        float cf2  = __shfl_sync(0xffffffffu, S1, 5, 16);  // lane 5 owns col 21
        __syncwarp();   // phase A reads complete before overwrite

        // ---- phase B: store cfp partials (constant cols), reduce ----
        #pragma unroll
        for (int k = 0; k < K; k++) sm[smb + 17*k + sub] = cfp[k];
        __syncwarp();
        int cT1 = (sub < 4) ? (16 + sub) : sub;
        float T0 = 0.f, T1 = 0.f;
        #pragma unroll
        for (int i = 0; i < 16; i++) {
            T0 += sm[smb + 17*sub + i];
            T1 += sm[smb + 17*cT1 + i];
        }

        // ---- lane-distributed epilogue (1-2 candidates per lane) ----
        {
            float lg = (q0.x + tpp - mean_a) * inv_a + beta_a;
            float cc = S0 - cvcf;
            float nn = q0.y - 2.f * T0 + cf2;
            float cosv = cc / fmaxf(n1 * sqrtf(nn), 1e-8f);
            lg *= fminf(fmaxf(1.f + cosv, 0.f), 1.f);
            best = lg; ksel = sub;
        }
        if (sub < 4) {
            float lg = (q1.x + tpp - mean_a) * inv_a + beta_a;
            float cc = S1 - cvcf;
            float nn = q1.y - 2.f * T1 + cf2;
            float cosv = cc / fmaxf(n1 * sqrtf(nn), 1e-8f);
            lg *= fminf(fmaxf(1.f + cosv, 0.f), 1.f);
            if (lg > best) { best = lg; ksel = 16 + sub; }
        }
    }

    // ---- argmax combine over 16 lanes (ties -> smallest k = first max) ----
    #pragma unroll
    for (int off = 1; off <= 8; off <<= 1) {
        float ob = __shfl_xor_sync(0xffffffffu, best, off);
        int   ok = __shfl_xor_sync(0xffffffffu, ksel, off);
        if (ob > best || (ob == best && ok < ksel)) { best = ob; ksel = ok; }
    }

    int nidx = __ldg(&adjp[ksel]);
    cf4 = __ldg(&((const float4*)(xTb + (size_t)nidx * C))[sub]);

    // ---- coalesced curve store + persist state (256B rows) ----
    ((float4*)(g_curves + ((size_t)step * NW + w) * C))[sub] = cf4;
    ((float4*)(g_curf + (size_t)w * C))[sub] = cf4;
    ((float4*)(g_pref + (size_t)w * C))[sub] = pf4;
    if (sub == 0) g_curidx[w] = nidx;

    if (step < STEPS - 1) {
        const float4* mv = (const float4*)mom_w;   // 2 rows x 32 float4
        float l0 = dot4(cf4, __ldg(&mv[sub]))      + dot4(pf4, __ldg(&mv[16 + sub]));
        float l1 = dot4(cf4, __ldg(&mv[32 + sub])) + dot4(pf4, __ldg(&mv[48 + sub]));
        #pragma unroll
        for (int off = 1; off <= 8; off <<= 1) {
            l0 += __shfl_xor_sync(0xffffffffu, l0, off);
            l1 += __shfl_xor_sync(0xffffffffu, l1, off);
        }
        if (sub == 0) {
            float inv0 = __ldg(&mom_gamma[0]) / sqrtf(__ldg(&mom_var[0]) + BN_EPS);
            float inv1 = __ldg(&mom_gamma[1]) / sqrtf(__ldg(&mom_var[1]) + BN_EPS);
            float m0 = (l0 - __ldg(&mom_mean[0])) * inv0 + __ldg(&mom_beta[0]);
            float m1 = (l1 - __ldg(&mom_mean[1])) * inv1 + __ldg(&mom_beta[1]);
            float mx = fmaxf(m0, m1);
            float e0 = expf(m0 - mx), e1 = expf(m1 - mx);
            float s = e0 + e1;
            g_S[b * 1024 + n]       = e0 / s;
            g_S[b * 1024 + 512 + n] = e1 / s;
        }
    }
}

// ---------------- reorder: g_curves[step][w][ch] -> out[b][ch][n][step] ----------------
__global__ __launch_bounds__(256)
void reorder_kernel(float* __restrict__ out) {
    __shared__ float tile[16][8 * C + 1];
    int b = blockIdx.x >> 5;
    int n0 = (blockIdx.x & 31) * 16;
    int t = threadIdx.x;

    #pragma unroll
    for (int step = 0; step < STEPS; step++) {
        #pragma unroll
        for (int i4 = 0; i4 < 4; i4++) {
            int i = i4 * 4 + (t >> 6);
            int ch = t & 63;
            int w = b * CN + n0 + i;
            tile[i][step * 64 + ch] =
                g_curves[((size_t)step * NW + w) * C + ch];
        }
    }
    __syncthreads();

    int i = t & 15, ch0 = t >> 4;
    #pragma unroll
    for (int cc = 0; cc < 4; cc++) {
        int ch = ch0 + cc * 16;
        float v[8];
        #pragma unroll
        for (int s = 0; s < STEPS; s++) v[s] = tile[i][s * 64 + ch];
        float4* dst = (float4*)(out +
            ((((size_t)b * C + ch) * CN) + n0 + i) * STEPS);
        dst[0] = make_float4(v[0], v[1], v[2], v[3]);
        dst[1] = make_float4(v[4], v[5], v[6], v[7]);
    }
}

extern "C" void kernel_launch(void* const* d_in, const int* in_sizes, int n_in,
                              void* d_out, int out_size) {
    const float* x          = (const float*)d_in[1];
    const int*   adj        = (const int*)  d_in[2];
    const int*   cur        = (const int*)  d_in[3];
    const float* agent_w    = (const float*)d_in[4];
    const float* agent_gamma= (const float*)d_in[5];
    const float* agent_beta = (const float*)d_in[6];
    const float* agent_mean = (const float*)d_in[7];
    const float* agent_var  = (const float*)d_in[8];
    const float* mom_w      = (const float*)d_in[9];
    const float* mom_gamma  = (const float*)d_in[10];
    const float* mom_beta   = (const float*)d_in[11];
    const float* mom_mean   = (const float*)d_in[12];
    const float* mom_var    = (const float*)d_in[13];
    float* out = (float*)d_out;

    dim3 pg(TOT / 32, BN);
    prep_kernel<<<pg, 256>>>(x, agent_w);

    int blocks = NW / 8;   // 1024 blocks of 128 threads (16 lanes/walker)
    walk_step_kernel<true><<<blocks, 128>>>(adj, cur, agent_w, agent_gamma,
        agent_beta, agent_mean, agent_var, mom_w, mom_gamma, mom_beta,
        mom_mean, mom_var, 0);
    for (int s = 1; s < STEPS; s++) {
        walk_step_kernel<false><<<blocks, 128>>>(adj, cur, agent_w, agent_gamma,
            agent_beta, agent_mean, agent_var, mom_w, mom_gamma, mom_beta,
            mom_mean, mom_var, s);
    }
    reorder_kernel<<<BN * (CN / 16), 256>>>(out);
}